// round 9
// baseline (speedup 1.0000x reference)
#include <cuda_runtime.h>
#include <cuda_bf16.h>
#include <stdint.h>

#define DI __device__ __forceinline__
typedef uint32_t u32;

#define N_ 256
#define D_ 128
#define NBI 512
#define ROWS_TOTAL (NBI * N_)       // 131072

#define KPW 68                      // u32 words per row in smem operand images
#define IMG_W (128 * KPW)           // 8704 words = 34816 B per image

// ---------------- global scratch (static: allowed) ----------------
__device__ float g_A[D_ * D_];
__device__ float g_C[D_ * D_];
__device__ __align__(16) float g_u[D_];
__device__ __align__(16) float g_w[D_];
__device__ __align__(16) float g_e[D_];
__device__ float g_c0;
__device__ float g_rj[ROWS_TOTAL], g_ck[ROWS_TOTAL];

__device__ u32 g_Shi[ROWS_TOTAL * 64];   // S split bf16 [row][64 words]
__device__ u32 g_Slo[ROWS_TOTAL * 64];
__device__ u32 g_Thi[ROWS_TOTAL * 64];   // T split bf16
__device__ u32 g_Tlo[ROWS_TOTAL * 64];
__device__ u32 g_Uthi[(size_t)NBI * 128 * 128];  // U^T split [bi][d][128 words]
__device__ u32 g_Utlo[(size_t)NBI * 128 * 128];
__device__ u32 g_WAhi[8192], g_WAlo[8192];       // A^T image [n][64 words]
__device__ u32 g_WChi[8192], g_WClo[8192];       // C^T image

// ---------------- helpers ----------------
DI u32 sa(const void* p) {
    u32 a; asm("{ .reg .u64 t; cvta.to.shared.u64 t, %1; cvt.u32.u64 %0, t; }" : "=r"(a) : "l"(p));
    return a;
}
DI void cpa16(u32 dst, const void* src) {
    asm volatile("cp.async.cg.shared.global [%0], [%1], 16;" :: "r"(dst), "l"(src) : "memory");
}
DI void cpa_wait() { asm volatile("cp.async.wait_all;" ::: "memory"); }

DI void split2(float v0, float v1, u32& hw, u32& lw) {
    __nv_bfloat16 h0 = __float2bfloat16(v0), h1 = __float2bfloat16(v1);
    float r0 = v0 - __bfloat162float(h0), r1 = v1 - __bfloat162float(h1);
    __nv_bfloat16 l0 = __float2bfloat16(r0), l1 = __float2bfloat16(r1);
    hw = (u32)__bfloat16_as_ushort(h0) | ((u32)__bfloat16_as_ushort(h1) << 16);
    lw = (u32)__bfloat16_as_ushort(l0) | ((u32)__bfloat16_as_ushort(l1) << 16);
}
DI void split1(float v, __nv_bfloat16& h, __nv_bfloat16& l) {
    h = __float2bfloat16(v);
    l = __float2bfloat16(v - __bfloat162float(h));
}

DI void ldm4(u32* r, u32 addr) {
    asm volatile("ldmatrix.sync.aligned.m8n8.x4.shared.b16 {%0,%1,%2,%3}, [%4];"
        : "=r"(r[0]), "=r"(r[1]), "=r"(r[2]), "=r"(r[3]) : "r"(addr));
}
DI void mma_bf16(float* c, u32 a0, u32 a1, u32 a2, u32 a3, u32 b0, u32 b1) {
    asm volatile(
        "mma.sync.aligned.m16n8k16.row.col.f32.bf16.bf16.f32 "
        "{%0,%1,%2,%3}, {%4,%5,%6,%7}, {%8,%9}, {%0,%1,%2,%3};"
        : "+f"(c[0]), "+f"(c[1]), "+f"(c[2]), "+f"(c[3])
        : "r"(a0), "r"(a1), "r"(a2), "r"(a3), "r"(b0), "r"(b1));
}

// K=128 product into warp tile 32(m) x 32(n) via ldmatrix; images [row][KPW words]
DI void mma_k128(float acc[2][4][4], u32 Ab, u32 Bb, int m0, int n0, int lane) {
    const u32 aoff = Ab + (u32)(((m0 + (lane & 15)) * KPW + ((lane >> 4) << 2)) * 4);
    const u32 boff = Bb + (u32)(((n0 + ((lane >> 4) << 3) + (lane & 7)) * KPW
                                 + (((lane >> 3) & 1) << 2)) * 4);
    #pragma unroll
    for (int ks = 0; ks < 8; ks++) {
        u32 a[2][4], b[2][4];
        #pragma unroll
        for (int mf = 0; mf < 2; mf++) ldm4(a[mf], aoff + (u32)(mf * 16 * KPW * 4) + ks * 32);
        #pragma unroll
        for (int ng = 0; ng < 2; ng++) ldm4(b[ng], boff + (u32)(ng * 16 * KPW * 4) + ks * 32);
        #pragma unroll
        for (int mf = 0; mf < 2; mf++)
            #pragma unroll
            for (int ng = 0; ng < 2; ng++) {
                mma_bf16(acc[mf][ng * 2],     a[mf][0], a[mf][1], a[mf][2], a[mf][3], b[ng][0], b[ng][1]);
                mma_bf16(acc[mf][ng * 2 + 1], a[mf][0], a[mf][1], a[mf][2], a[mf][3], b[ng][2], b[ng][3]);
            }
    }
}
DI void gemm3p(float acc[2][4][4], u32 AH, u32 AL, u32 BH, u32 BL, int m0, int n0, int lane) {
    mma_k128(acc, AH, BH, m0, n0, lane);
    mma_k128(acc, AH, BL, m0, n0, lane);
    mma_k128(acc, AL, BH, m0, n0, lane);
}

// =======================================================================
// k_pre: fold weights (fp32, proven)
// =======================================================================
__global__ void __launch_bounds__(128) k_pre(
    const float* __restrict__ Wq, const float* __restrict__ bq,
    const float* __restrict__ Wk, const float* __restrict__ bk,
    const float* __restrict__ Wv, const float* __restrict__ bv,
    const float* __restrict__ Wo)
{
    extern __shared__ float sWq[];
    const float ISD = 0.08838834764831845f;
    const int tid = threadIdx.x;
    const int a = blockIdx.x;

    if (a < 128) {
        for (int idx = tid; idx < D_ * D_; idx += 128) {
            int r = idx >> 7, c = idx & 127;
            sWq[r * 129 + c] = Wq[idx];
        }
        __syncthreads();
        float accA = 0.f, accC = 0.f;
        #pragma unroll 16
        for (int d = 0; d < D_; d++) {
            accA += __ldg(&Wk[a * D_ + d]) * sWq[tid * 129 + d];
            accC += __ldg(&Wv[a * D_ + d]) * __ldg(&Wo[d * D_ + tid]);
        }
        g_A[a * D_ + tid] = accA * ISD;
        g_C[a * D_ + tid] = accC;
    } else if (a == 128) {
        for (int idx = tid; idx < D_ * D_; idx += 128) {
            int r = idx >> 7, c = idx & 127;
            sWq[r * 129 + c] = Wk[idx];
        }
        float* sred = sWq + 128 * 129;
        sred[tid] = bk[tid] * bq[tid];
        __syncthreads();
        float su = 0.f;
        #pragma unroll 16
        for (int d = 0; d < D_; d++) su += sWq[tid * 129 + d] * __ldg(&bq[d]);
        g_u[tid] = su * ISD;
        if (tid == 0) {
            float c = 0.f;
            #pragma unroll 16
            for (int d = 0; d < D_; d++) c += sred[d];
            g_c0 = c * ISD;
        }
    } else if (a == 129) {
        for (int idx = tid; idx < D_ * D_; idx += 128) {
            int r = idx >> 7, c = idx & 127;
            sWq[r * 129 + c] = Wq[idx];
        }
        __syncthreads();
        float sw = 0.f;
        #pragma unroll 16
        for (int d = 0; d < D_; d++) sw += sWq[tid * 129 + d] * __ldg(&bk[d]);
        g_w[tid] = sw * ISD;
    } else {
        float se = 0.f;
        #pragma unroll 16
        for (int d = 0; d < D_; d++) se += __ldg(&bv[d]) * __ldg(&Wo[d * D_ + tid]);
        g_e[tid] = se;
    }
}

// =======================================================================
// k_prew: split W^T images (rows = out col n, cols = k)
// =======================================================================
__global__ void __launch_bounds__(256) k_prew()
{
    const int tid = threadIdx.x;
    for (int w = tid; w < 8192; w += 256) {
        int n = w >> 6, d0 = (w & 63) * 2;
        u32 hw, lw;
        split2(g_A[d0 * 128 + n], g_A[(d0 + 1) * 128 + n], hw, lw);
        g_WAhi[w] = hw; g_WAlo[w] = lw;
        split2(g_C[d0 * 128 + n], g_C[(d0 + 1) * 128 + n], hw, lw);
        g_WChi[w] = hw; g_WClo[w] = lw;
    }
}

// =======================================================================
// k_split: S fp32 -> split bf16 gmem + rj/ck dots. grid 1024 x 256
// =======================================================================
__global__ void __launch_bounds__(256) k_split(const float* __restrict__ S)
{
    const int lane = threadIdx.x & 31;
    const int wg = blockIdx.x * 8 + (threadIdx.x >> 5);
    const float4 uv = *reinterpret_cast<const float4*>(&g_u[lane * 4]);
    const float4 wv = *reinterpret_cast<const float4*>(&g_w[lane * 4]);
    const float c0 = g_c0;

    for (int i = 0; i < 16; i++) {
        const long row = (long)wg * 16 + i;
        float4 s = __ldg(reinterpret_cast<const float4*>(&S[row * D_ + lane * 4]));
        float du = s.x * uv.x + s.y * uv.y + s.z * uv.z + s.w * uv.w;
        float dw = s.x * wv.x + s.y * wv.y + s.z * wv.z + s.w * wv.w;
        #pragma unroll
        for (int off = 16; off > 0; off >>= 1) {
            du += __shfl_xor_sync(0xFFFFFFFFu, du, off);
            dw += __shfl_xor_sync(0xFFFFFFFFu, dw, off);
        }
        if (lane == 0) { g_rj[row] = du + c0; g_ck[row] = dw; }
        u32 h0, l0, h1, l1;
        split2(s.x, s.y, h0, l0);
        split2(s.z, s.w, h1, l1);
        g_Shi[row * 64 + lane * 2]     = h0;
        g_Shi[row * 64 + lane * 2 + 1] = h1;
        g_Slo[row * 64 + lane * 2]     = l0;
        g_Slo[row * 64 + lane * 2 + 1] = l1;
    }
}

// =======================================================================
// k_proj: T = S@A and U = S@C in one CTA.  grid 1024, block 512 (16 warps,
// warp tile 32x32), smem 6 images (S hi/lo, WA hi/lo, WC hi/lo).
// =======================================================================
#define PJ_SMEM (6 * IMG_W * 4)

__global__ void __launch_bounds__(512) k_proj()
{
    extern __shared__ u32 smp[];
    u32* SHI = smp;
    u32* SLO = SHI + IMG_W;
    u32* WAH = SLO + IMG_W;
    u32* WAL = WAH + IMG_W;
    u32* WCH = WAL + IMG_W;
    u32* WCL = WCH + IMG_W;

    const int tid = threadIdx.x;
    const int warp = tid >> 5, lane = tid & 31;
    const int g = lane >> 2, t = lane & 3;
    const int m0 = (warp & 3) * 32, n0 = (warp >> 2) * 32;
    const long rb = (long)blockIdx.x * 128;

    const u32 aSHI = sa(SHI), aSLO = sa(SLO), aWAH = sa(WAH), aWAL = sa(WAL),
              aWCH = sa(WCH), aWCL = sa(WCL);

    for (int i = tid; i < 2048; i += 512) {
        int r = i >> 4, c4 = (i & 15) << 2;
        u32 doff = (u32)((r * KPW + c4) * 4);
        cpa16(aSHI + doff, g_Shi + rb * 64 + r * 64 + c4);
        cpa16(aSLO + doff, g_Slo + rb * 64 + r * 64 + c4);
        cpa16(aWAH + doff, g_WAhi + r * 64 + c4);
        cpa16(aWAL + doff, g_WAlo + r * 64 + c4);
        cpa16(aWCH + doff, g_WChi + r * 64 + c4);
        cpa16(aWCL + doff, g_WClo + r * 64 + c4);
    }
    cpa_wait();
    __syncthreads();

    float acc[2][4][4];
    #pragma unroll
    for (int mf = 0; mf < 2; mf++)
        #pragma unroll
        for (int nf = 0; nf < 4; nf++)
            #pragma unroll
            for (int q = 0; q < 4; q++) acc[mf][nf][q] = 0.f;

    // ---- T = S @ A ----
    gemm3p(acc, aSHI, aSLO, aWAH, aWAL, m0, n0, lane);
    #pragma unroll
    for (int mf = 0; mf < 2; mf++)
        #pragma unroll
        for (int half = 0; half < 2; half++) {
            const long r = rb + m0 + mf * 16 + g + half * 8;
            #pragma unroll
            for (int nf = 0; nf < 4; nf++) {
                const int cw = (n0 + nf * 8) / 2 + t;
                u32 hw, lw;
                split2(acc[mf][nf][half * 2], acc[mf][nf][half * 2 + 1], hw, lw);
                g_Thi[r * 64 + cw] = hw;
                g_Tlo[r * 64 + cw] = lw;
            }
        }
    __syncthreads();   // all warps done reading WA images

    // ---- U = S @ C ----
    #pragma unroll
    for (int mf = 0; mf < 2; mf++)
        #pragma unroll
        for (int nf = 0; nf < 4; nf++)
            #pragma unroll
            for (int q = 0; q < 4; q++) acc[mf][nf][q] = 0.f;
    gemm3p(acc, aSHI, aSLO, aWCH, aWCL, m0, n0, lane);

    // transpose U into WA area (free now): OH/OL [d][128 kk] bf16, stride 136
    __nv_bfloat16* oh = (__nv_bfloat16*)WAH;
    __nv_bfloat16* ol = (__nv_bfloat16*)WAL;
    #pragma unroll
    for (int mf = 0; mf < 2; mf++)
        #pragma unroll
        for (int half = 0; half < 2; half++) {
            const int kkL = m0 + mf * 16 + g + half * 8;
            #pragma unroll
            for (int nf = 0; nf < 4; nf++) {
                const int d0 = n0 + nf * 8 + 2 * t;
                __nv_bfloat16 h, l;
                split1(acc[mf][nf][half * 2], h, l);
                oh[d0 * 136 + kkL] = h; ol[d0 * 136 + kkL] = l;
                split1(acc[mf][nf][half * 2 + 1], h, l);
                oh[(d0 + 1) * 136 + kkL] = h; ol[(d0 + 1) * 136 + kkL] = l;
            }
        }
    __syncthreads();

    const int bi = blockIdx.x >> 1;
    const int kh = blockIdx.x & 1;
    for (int w = tid; w < 8192; w += 512) {
        int d = w >> 6, c = w & 63;
        const long go = ((long)bi * 128 + d) * 128 + kh * 64 + c;
        g_Uthi[go] = WAH[d * KPW + c];
        g_Utlo[go] = WAL[d * KPW + c];
    }
}

// =======================================================================
// k_attn: per (bi, jh): GEMM1 -> relu/bias/rowsum -> P -> GEMM2; fused
// residual + LayerNorm.  grid 1024, block 512, smem 6 images + ~3KB.
// =======================================================================
#define KA_SMEM (6 * IMG_W * 4 + (128 + 256 + 128 + 128 + 128) * 4)

__global__ void __launch_bounds__(512) k_attn(
    const float* __restrict__ S, const float* __restrict__ bo,
    const float* __restrict__ ln_g, const float* __restrict__ ln_b,
    float* __restrict__ out)
{
    extern __shared__ u32 sma[];
    u32* THI = sma;
    u32* TLO = THI + IMG_W;
    u32* PHI = TLO + IMG_W;    // S tile, later P
    u32* PLO = PHI + IMG_W;
    u32* UHI = PLO + IMG_W;
    u32* ULO = UHI + IMG_W;
    float* srj   = (float*)(ULO + IMG_W);  // 128
    float* sck   = srj + 128;              // 256
    float* sRow  = sck + 256;              // 128
    float* sMu   = sRow + 128;             // 128
    float* sRstd = sMu + 128;              // 128
    float* sx    = (float*)THI;            // epilogue overlay [128][133]

    const int tid = threadIdx.x;
    const int warp = tid >> 5, lane = tid & 31;
    const int g = lane >> 2, t = lane & 3;
    const int m0 = (warp & 3) * 32, n0 = (warp >> 2) * 32;

    const int bij = blockIdx.x;
    const int bi = bij >> 1, jh = bij & 1;
    const long rT = (long)bij * 128;

    const u32 aTHI = sa(THI), aTLO = sa(TLO), aPHI = sa(PHI), aPLO = sa(PLO),
              aUHI = sa(UHI), aULO = sa(ULO);

    for (int i = tid; i < 2048; i += 512) {
        int r = i >> 4, c4 = (i & 15) << 2;
        u32 doff = (u32)((r * KPW + c4) * 4);
        cpa16(aTHI + doff, g_Thi + rT * 64 + r * 64 + c4);
        cpa16(aTLO + doff, g_Tlo + rT * 64 + r * 64 + c4);
    }
    if (tid < 128) { srj[tid] = g_rj[rT + tid]; sRow[tid] = 0.f; }
    if (tid < 256) sck[tid] = g_ck[(long)bi * 256 + tid];

    float acc2[2][4][4];
    #pragma unroll
    for (int mf = 0; mf < 2; mf++)
        #pragma unroll
        for (int nf = 0; nf < 4; nf++)
            #pragma unroll
            for (int q = 0; q < 4; q++) acc2[mf][nf][q] = 0.f;

    for (int t2 = 0; t2 < 2; t2++) {
        __syncthreads();   // prev GEMM2 done; (t2==0) srj/sck/sRow visible
        const long sr = ((long)bi * 256 + t2 * 128) * 64;
        for (int i = tid; i < 2048; i += 512) {
            int r = i >> 4, c4 = (i & 15) << 2;
            u32 doff = (u32)((r * KPW + c4) * 4);
            cpa16(aPHI + doff, g_Shi + sr + r * 64 + c4);
            cpa16(aPLO + doff, g_Slo + sr + r * 64 + c4);
            const long go = ((long)bi * 128 + r) * 128 + t2 * 64 + c4;
            cpa16(aUHI + doff, g_Uthi + go);
            cpa16(aULO + doff, g_Utlo + go);
        }
        cpa_wait();
        __syncthreads();

        // GEMM1: scores = T . S^T
        float acc1[2][4][4];
        #pragma unroll
        for (int mf = 0; mf < 2; mf++)
            #pragma unroll
            for (int nf = 0; nf < 4; nf++)
                #pragma unroll
                for (int q = 0; q < 4; q++) acc1[mf][nf][q] = 0.f;
        gemm3p(acc1, aTHI, aTLO, aPHI, aPLO, m0, n0, lane);
        __syncthreads();   // all warps done reading S tile

        // P = relu(scores + rj + ck) -> PHI/PLO, rowsum
        #pragma unroll
        for (int mf = 0; mf < 2; mf++)
            #pragma unroll
            for (int half = 0; half < 2; half++) {
                const int j = m0 + mf * 16 + g + half * 8;
                const float rj = srj[j];
                float rsum = 0.f;
                #pragma unroll
                for (int nf = 0; nf < 4; nf++) {
                    const int kk = n0 + nf * 8 + 2 * t;
                    float p0 = fmaxf(acc1[mf][nf][half * 2]     + rj + sck[t2 * 128 + kk],     0.f);
                    float p1 = fmaxf(acc1[mf][nf][half * 2 + 1] + rj + sck[t2 * 128 + kk + 1], 0.f);
                    rsum += p0 + p1;
                    u32 hw, lw;
                    split2(p0, p1, hw, lw);
                    const int cw = (n0 + nf * 8) / 2 + t;
                    PHI[j * KPW + cw] = hw;
                    PLO[j * KPW + cw] = lw;
                }
                rsum += __shfl_xor_sync(0xFFFFFFFFu, rsum, 1);
                rsum += __shfl_xor_sync(0xFFFFFFFFu, rsum, 2);
                if (t == 0) atomicAdd(&sRow[j], rsum);
            }
        __syncthreads();

        // GEMM2: out += P . U^T
        gemm3p(acc2, aPHI, aPLO, aUHI, aULO, m0, n0, lane);
    }
    __syncthreads();   // sRow final; THI/TLO free

    // epilogue: x = out + rowsum*e + bo + S  -> sx
    const float* Sb = S + ((long)bi * 256 + jh * 128) * D_;
    #pragma unroll
    for (int mf = 0; mf < 2; mf++)
        #pragma unroll
        for (int half = 0; half < 2; half++) {
            const int j = m0 + mf * 16 + g + half * 8;
            const float rs = sRow[j];
            #pragma unroll
            for (int nf = 0; nf < 4; nf++) {
                const int d = n0 + nf * 8 + 2 * t;
                float2 sv = __ldg(reinterpret_cast<const float2*>(&Sb[(long)j * D_ + d]));
                float x0 = acc2[mf][nf][half * 2]     + rs * __ldg(&g_e[d])     + __ldg(&bo[d])     + sv.x;
                float x1 = acc2[mf][nf][half * 2 + 1] + rs * __ldg(&g_e[d + 1]) + __ldg(&bo[d + 1]) + sv.y;
                sx[j * 133 + d]     = x0;
                sx[j * 133 + d + 1] = x1;
            }
        }
    __syncthreads();

    if (tid < 128) {
        float s = 0.f, s2 = 0.f;
        #pragma unroll 8
        for (int d = 0; d < D_; d++) {
            float v = sx[tid * 133 + d];
            s += v; s2 += v * v;
        }
        float mu = s * (1.f / 128.f);
        float var = s2 * (1.f / 128.f) - mu * mu;
        sMu[tid] = mu;
        sRstd[tid] = rsqrtf(var + 1e-5f);
    }
    __syncthreads();

    float* op = out + ((long)bi * 256 + jh * 128) * D_;
    for (int idx = tid; idx < 128 * D_; idx += 512) {
        int j = idx >> 7, d = idx & 127;
        op[idx] = (sx[j * 133 + d] - sMu[j]) * sRstd[j] * __ldg(&ln_g[d]) + __ldg(&ln_b[d]);
    }
}

// =======================================================================
// launch
// =======================================================================
extern "C" void kernel_launch(void* const* d_in, const int* in_sizes, int n_in,
                              void* d_out, int out_size)
{
    (void)in_sizes; (void)n_in; (void)out_size;
    const float* S    = (const float*)d_in[1];
    const float* Wq   = (const float*)d_in[2];
    const float* bq   = (const float*)d_in[3];
    const float* Wk   = (const float*)d_in[4];
    const float* bk   = (const float*)d_in[5];
    const float* Wv   = (const float*)d_in[6];
    const float* bv   = (const float*)d_in[7];
    const float* Wo   = (const float*)d_in[8];
    const float* bo   = (const float*)d_in[9];
    const float* ln_g = (const float*)d_in[10];
    const float* ln_b = (const float*)d_in[11];
    float* out = (float*)d_out;

    const size_t sm0 = (size_t)(128 * 129 + 128) * sizeof(float);
    cudaFuncSetAttribute(k_pre,  cudaFuncAttributeMaxDynamicSharedMemorySize, (int)sm0);
    cudaFuncSetAttribute(k_proj, cudaFuncAttributeMaxDynamicSharedMemorySize, PJ_SMEM);
    cudaFuncSetAttribute(k_attn, cudaFuncAttributeMaxDynamicSharedMemorySize, KA_SMEM);

    k_pre  <<<131, 128, sm0>>>(Wq, bq, Wk, bk, Wv, bv, Wo);
    k_prew <<<1, 256>>>();
    k_split<<<1024, 256>>>(S);
    k_proj <<<1024, 512, PJ_SMEM>>>();
    k_attn <<<1024, 512, KA_SMEM>>>(S, bo, ln_g, ln_b, out);
}

// round 10
// speedup vs baseline: 1.2730x; 1.2730x over previous
#include <cuda_runtime.h>
#include <cuda_bf16.h>
#include <stdint.h>

#define DI __device__ __forceinline__
typedef uint32_t u32;

#define N_ 256
#define D_ 128
#define NBI 512
#define ROWS_TOTAL (NBI * N_)       // 131072

#define KPW 68                      // u32 words per row in smem operand images
#define IMG_W (128 * KPW)           // 8704 words = 34816 B per image

// ---------------- global scratch (static: allowed) ----------------
__device__ float g_A[D_ * D_];
__device__ float g_C[D_ * D_];
__device__ __align__(16) float g_u[D_];
__device__ __align__(16) float g_w[D_];
__device__ __align__(16) float g_e[D_];
__device__ float g_c0;
__device__ float g_rj[ROWS_TOTAL], g_ck[ROWS_TOTAL];

__device__ u32 g_Shi[ROWS_TOTAL * 64];   // S split bf16 [row][64 words]
__device__ u32 g_Slo[ROWS_TOTAL * 64];
__device__ u32 g_Thi[ROWS_TOTAL * 64];   // T split bf16
__device__ u32 g_Tlo[ROWS_TOTAL * 64];
__device__ u32 g_Uthi[(size_t)NBI * 128 * 128];  // U^T split [bi][d][128 words]
__device__ u32 g_Utlo[(size_t)NBI * 128 * 128];
__device__ u32 g_WAhi[8192], g_WAlo[8192];       // A^T image [n][64 words]
__device__ u32 g_WChi[8192], g_WClo[8192];       // C^T image

// ---------------- helpers ----------------
DI u32 sa(const void* p) {
    u32 a; asm("{ .reg .u64 t; cvta.to.shared.u64 t, %1; cvt.u32.u64 %0, t; }" : "=r"(a) : "l"(p));
    return a;
}
DI void cpa16(u32 dst, const void* src) {
    asm volatile("cp.async.cg.shared.global [%0], [%1], 16;" :: "r"(dst), "l"(src) : "memory");
}
DI void cpa_wait() { asm volatile("cp.async.wait_all;" ::: "memory"); }

DI void split2(float v0, float v1, u32& hw, u32& lw) {
    __nv_bfloat16 h0 = __float2bfloat16(v0), h1 = __float2bfloat16(v1);
    float r0 = v0 - __bfloat162float(h0), r1 = v1 - __bfloat162float(h1);
    __nv_bfloat16 l0 = __float2bfloat16(r0), l1 = __float2bfloat16(r1);
    hw = (u32)__bfloat16_as_ushort(h0) | ((u32)__bfloat16_as_ushort(h1) << 16);
    lw = (u32)__bfloat16_as_ushort(l0) | ((u32)__bfloat16_as_ushort(l1) << 16);
}
DI void split1(float v, __nv_bfloat16& h, __nv_bfloat16& l) {
    h = __float2bfloat16(v);
    l = __float2bfloat16(v - __bfloat162float(h));
}

DI void ldm4(u32* r, u32 addr) {
    asm volatile("ldmatrix.sync.aligned.m8n8.x4.shared.b16 {%0,%1,%2,%3}, [%4];"
        : "=r"(r[0]), "=r"(r[1]), "=r"(r[2]), "=r"(r[3]) : "r"(addr));
}
DI void mma_bf16(float* c, u32 a0, u32 a1, u32 a2, u32 a3, u32 b0, u32 b1) {
    asm volatile(
        "mma.sync.aligned.m16n8k16.row.col.f32.bf16.bf16.f32 "
        "{%0,%1,%2,%3}, {%4,%5,%6,%7}, {%8,%9}, {%0,%1,%2,%3};"
        : "+f"(c[0]), "+f"(c[1]), "+f"(c[2]), "+f"(c[3])
        : "r"(a0), "r"(a1), "r"(a2), "r"(a3), "r"(b0), "r"(b1));
}

// Fused 3-product split GEMM (hi*hi + hi*lo + lo*hi), warp tile 32x32.
// Per ks step: 8 ldmatrix (A hi+lo once, B hi then B lo) and 24 MMAs.
DI void gemm3p(float acc[2][4][4], u32 AH, u32 AL, u32 BH, u32 BL,
               int m0, int n0, int lane) {
    const u32 arow = (u32)(((m0 + (lane & 15)) * KPW + ((lane >> 4) << 2)) * 4);
    const u32 brow = (u32)(((n0 + ((lane >> 4) << 3) + (lane & 7)) * KPW
                            + (((lane >> 3) & 1) << 2)) * 4);
    const u32 aoffH = AH + arow, aoffL = AL + arow;
    const u32 boffH = BH + brow, boffL = BL + brow;
    #pragma unroll
    for (int ks = 0; ks < 8; ks++) {
        u32 aH[2][4], aL[2][4], b[2][4];
        #pragma unroll
        for (int mf = 0; mf < 2; mf++) {
            ldm4(aH[mf], aoffH + (u32)(mf * 16 * KPW * 4) + ks * 32);
            ldm4(aL[mf], aoffL + (u32)(mf * 16 * KPW * 4) + ks * 32);
        }
        // B hi: hi*hi and lo*hi
        #pragma unroll
        for (int ng = 0; ng < 2; ng++) ldm4(b[ng], boffH + (u32)(ng * 16 * KPW * 4) + ks * 32);
        #pragma unroll
        for (int mf = 0; mf < 2; mf++)
            #pragma unroll
            for (int ng = 0; ng < 2; ng++) {
                mma_bf16(acc[mf][ng * 2],     aH[mf][0], aH[mf][1], aH[mf][2], aH[mf][3], b[ng][0], b[ng][1]);
                mma_bf16(acc[mf][ng * 2 + 1], aH[mf][0], aH[mf][1], aH[mf][2], aH[mf][3], b[ng][2], b[ng][3]);
                mma_bf16(acc[mf][ng * 2],     aL[mf][0], aL[mf][1], aL[mf][2], aL[mf][3], b[ng][0], b[ng][1]);
                mma_bf16(acc[mf][ng * 2 + 1], aL[mf][0], aL[mf][1], aL[mf][2], aL[mf][3], b[ng][2], b[ng][3]);
            }
        // B lo: hi*lo
        #pragma unroll
        for (int ng = 0; ng < 2; ng++) ldm4(b[ng], boffL + (u32)(ng * 16 * KPW * 4) + ks * 32);
        #pragma unroll
        for (int mf = 0; mf < 2; mf++)
            #pragma unroll
            for (int ng = 0; ng < 2; ng++) {
                mma_bf16(acc[mf][ng * 2],     aH[mf][0], aH[mf][1], aH[mf][2], aH[mf][3], b[ng][0], b[ng][1]);
                mma_bf16(acc[mf][ng * 2 + 1], aH[mf][0], aH[mf][1], aH[mf][2], aH[mf][3], b[ng][2], b[ng][3]);
            }
    }
}

// =======================================================================
// k_pre: fold weights (fp32, proven)
// =======================================================================
__global__ void __launch_bounds__(128) k_pre(
    const float* __restrict__ Wq, const float* __restrict__ bq,
    const float* __restrict__ Wk, const float* __restrict__ bk,
    const float* __restrict__ Wv, const float* __restrict__ bv,
    const float* __restrict__ Wo)
{
    extern __shared__ float sWq[];
    const float ISD = 0.08838834764831845f;
    const int tid = threadIdx.x;
    const int a = blockIdx.x;

    if (a < 128) {
        for (int idx = tid; idx < D_ * D_; idx += 128) {
            int r = idx >> 7, c = idx & 127;
            sWq[r * 129 + c] = Wq[idx];
        }
        __syncthreads();
        float accA = 0.f, accC = 0.f;
        #pragma unroll 16
        for (int d = 0; d < D_; d++) {
            accA += __ldg(&Wk[a * D_ + d]) * sWq[tid * 129 + d];
            accC += __ldg(&Wv[a * D_ + d]) * __ldg(&Wo[d * D_ + tid]);
        }
        g_A[a * D_ + tid] = accA * ISD;
        g_C[a * D_ + tid] = accC;
    } else if (a == 128) {
        for (int idx = tid; idx < D_ * D_; idx += 128) {
            int r = idx >> 7, c = idx & 127;
            sWq[r * 129 + c] = Wk[idx];
        }
        float* sred = sWq + 128 * 129;
        sred[tid] = bk[tid] * bq[tid];
        __syncthreads();
        float su = 0.f;
        #pragma unroll 16
        for (int d = 0; d < D_; d++) su += sWq[tid * 129 + d] * __ldg(&bq[d]);
        g_u[tid] = su * ISD;
        if (tid == 0) {
            float c = 0.f;
            #pragma unroll 16
            for (int d = 0; d < D_; d++) c += sred[d];
            g_c0 = c * ISD;
        }
    } else if (a == 129) {
        for (int idx = tid; idx < D_ * D_; idx += 128) {
            int r = idx >> 7, c = idx & 127;
            sWq[r * 129 + c] = Wq[idx];
        }
        __syncthreads();
        float sw = 0.f;
        #pragma unroll 16
        for (int d = 0; d < D_; d++) sw += sWq[tid * 129 + d] * __ldg(&bk[d]);
        g_w[tid] = sw * ISD;
    } else {
        float se = 0.f;
        #pragma unroll 16
        for (int d = 0; d < D_; d++) se += __ldg(&bv[d]) * __ldg(&Wo[d * D_ + tid]);
        g_e[tid] = se;
    }
}

// =======================================================================
// k_prew: split W^T images (rows = out col n, cols = k)
// =======================================================================
__global__ void __launch_bounds__(256) k_prew()
{
    const int tid = threadIdx.x;
    for (int w = tid; w < 8192; w += 256) {
        int n = w >> 6, d0 = (w & 63) * 2;
        u32 hw, lw;
        split2(g_A[d0 * 128 + n], g_A[(d0 + 1) * 128 + n], hw, lw);
        g_WAhi[w] = hw; g_WAlo[w] = lw;
        split2(g_C[d0 * 128 + n], g_C[(d0 + 1) * 128 + n], hw, lw);
        g_WChi[w] = hw; g_WClo[w] = lw;
    }
}

// =======================================================================
// k_split: S fp32 -> split bf16 gmem + rj/ck dots. grid 1024 x 256
// =======================================================================
__global__ void __launch_bounds__(256) k_split(const float* __restrict__ S)
{
    const int lane = threadIdx.x & 31;
    const int wg = blockIdx.x * 8 + (threadIdx.x >> 5);
    const float4 uv = *reinterpret_cast<const float4*>(&g_u[lane * 4]);
    const float4 wv = *reinterpret_cast<const float4*>(&g_w[lane * 4]);
    const float c0 = g_c0;

    for (int i = 0; i < 16; i++) {
        const long row = (long)wg * 16 + i;
        float4 s = __ldg(reinterpret_cast<const float4*>(&S[row * D_ + lane * 4]));
        float du = s.x * uv.x + s.y * uv.y + s.z * uv.z + s.w * uv.w;
        float dw = s.x * wv.x + s.y * wv.y + s.z * wv.z + s.w * wv.w;
        #pragma unroll
        for (int off = 16; off > 0; off >>= 1) {
            du += __shfl_xor_sync(0xFFFFFFFFu, du, off);
            dw += __shfl_xor_sync(0xFFFFFFFFu, dw, off);
        }
        if (lane == 0) { g_rj[row] = du + c0; g_ck[row] = dw; }
        u32 h0, l0, h1, l1;
        split2(s.x, s.y, h0, l0);
        split2(s.z, s.w, h1, l1);
        g_Shi[row * 64 + lane * 2]     = h0;
        g_Shi[row * 64 + lane * 2 + 1] = h1;
        g_Slo[row * 64 + lane * 2]     = l0;
        g_Slo[row * 64 + lane * 2 + 1] = l1;
    }
}

// =======================================================================
// k_proj: T = S@A and U = S@C in one CTA.  grid 1024, block 512 (16 warps,
// warp tile 32x32), smem 6 images (S hi/lo, WA hi/lo, WC hi/lo).
// =======================================================================
#define PJ_SMEM (6 * IMG_W * 4)

__global__ void __launch_bounds__(512) k_proj()
{
    extern __shared__ u32 smp[];
    u32* SHI = smp;
    u32* SLO = SHI + IMG_W;
    u32* WAH = SLO + IMG_W;
    u32* WAL = WAH + IMG_W;
    u32* WCH = WAL + IMG_W;
    u32* WCL = WCH + IMG_W;

    const int tid = threadIdx.x;
    const int warp = tid >> 5, lane = tid & 31;
    const int g = lane >> 2, t = lane & 3;
    const int m0 = (warp & 3) * 32, n0 = (warp >> 2) * 32;
    const long rb = (long)blockIdx.x * 128;

    const u32 aSHI = sa(SHI), aSLO = sa(SLO), aWAH = sa(WAH), aWAL = sa(WAL),
              aWCH = sa(WCH), aWCL = sa(WCL);

    for (int i = tid; i < 2048; i += 512) {
        int r = i >> 4, c4 = (i & 15) << 2;
        u32 doff = (u32)((r * KPW + c4) * 4);
        cpa16(aSHI + doff, g_Shi + rb * 64 + r * 64 + c4);
        cpa16(aSLO + doff, g_Slo + rb * 64 + r * 64 + c4);
        cpa16(aWAH + doff, g_WAhi + r * 64 + c4);
        cpa16(aWAL + doff, g_WAlo + r * 64 + c4);
        cpa16(aWCH + doff, g_WChi + r * 64 + c4);
        cpa16(aWCL + doff, g_WClo + r * 64 + c4);
    }
    cpa_wait();
    __syncthreads();

    float acc[2][4][4];
    #pragma unroll
    for (int mf = 0; mf < 2; mf++)
        #pragma unroll
        for (int nf = 0; nf < 4; nf++)
            #pragma unroll
            for (int q = 0; q < 4; q++) acc[mf][nf][q] = 0.f;

    // ---- T = S @ A ----
    gemm3p(acc, aSHI, aSLO, aWAH, aWAL, m0, n0, lane);
    #pragma unroll
    for (int mf = 0; mf < 2; mf++)
        #pragma unroll
        for (int half = 0; half < 2; half++) {
            const long r = rb + m0 + mf * 16 + g + half * 8;
            #pragma unroll
            for (int nf = 0; nf < 4; nf++) {
                const int cw = (n0 + nf * 8) / 2 + t;
                u32 hw, lw;
                split2(acc[mf][nf][half * 2], acc[mf][nf][half * 2 + 1], hw, lw);
                g_Thi[r * 64 + cw] = hw;
                g_Tlo[r * 64 + cw] = lw;
            }
        }
    __syncthreads();   // all warps done reading WA images

    // ---- U = S @ C ----
    #pragma unroll
    for (int mf = 0; mf < 2; mf++)
        #pragma unroll
        for (int nf = 0; nf < 4; nf++)
            #pragma unroll
            for (int q = 0; q < 4; q++) acc[mf][nf][q] = 0.f;
    gemm3p(acc, aSHI, aSLO, aWCH, aWCL, m0, n0, lane);

    // transpose U into WA area (free now): OH/OL [d][128 kk] bf16, stride 136
    __nv_bfloat16* oh = (__nv_bfloat16*)WAH;
    __nv_bfloat16* ol = (__nv_bfloat16*)WAL;
    #pragma unroll
    for (int mf = 0; mf < 2; mf++)
        #pragma unroll
        for (int half = 0; half < 2; half++) {
            const int kkL = m0 + mf * 16 + g + half * 8;
            #pragma unroll
            for (int nf = 0; nf < 4; nf++) {
                const int d0 = n0 + nf * 8 + 2 * t;
                __nv_bfloat16 h, l;
                split1(acc[mf][nf][half * 2], h, l);
                oh[d0 * 136 + kkL] = h; ol[d0 * 136 + kkL] = l;
                split1(acc[mf][nf][half * 2 + 1], h, l);
                oh[(d0 + 1) * 136 + kkL] = h; ol[(d0 + 1) * 136 + kkL] = l;
            }
        }
    __syncthreads();

    const int bi = blockIdx.x >> 1;
    const int kh = blockIdx.x & 1;
    for (int w = tid; w < 8192; w += 512) {
        int d = w >> 6, c = w & 63;
        const long go = ((long)bi * 128 + d) * 128 + kh * 64 + c;
        g_Uthi[go] = WAH[d * KPW + c];
        g_Utlo[go] = WAL[d * KPW + c];
    }
}

// =======================================================================
// k_attn: per (bi, jh): GEMM1 -> relu/bias/rowsum -> P -> GEMM2; fused
// residual + LayerNorm.  grid 1024, block 512, smem 6 images + ~3KB.
// =======================================================================
#define KA_SMEM (6 * IMG_W * 4 + (128 + 256 + 128 + 128 + 128) * 4)

__global__ void __launch_bounds__(512) k_attn(
    const float* __restrict__ S, const float* __restrict__ bo,
    const float* __restrict__ ln_g, const float* __restrict__ ln_b,
    float* __restrict__ out)
{
    extern __shared__ u32 sma[];
    u32* THI = sma;
    u32* TLO = THI + IMG_W;
    u32* PHI = TLO + IMG_W;    // S tile, later P
    u32* PLO = PHI + IMG_W;
    u32* UHI = PLO + IMG_W;
    u32* ULO = UHI + IMG_W;
    float* srj   = (float*)(ULO + IMG_W);  // 128
    float* sck   = srj + 128;              // 256
    float* sRow  = sck + 256;              // 128
    float* sMu   = sRow + 128;             // 128
    float* sRstd = sMu + 128;              // 128
    float* sx    = (float*)THI;            // epilogue overlay [128][133]

    const int tid = threadIdx.x;
    const int warp = tid >> 5, lane = tid & 31;
    const int g = lane >> 2, t = lane & 3;
    const int m0 = (warp & 3) * 32, n0 = (warp >> 2) * 32;

    const int bij = blockIdx.x;
    const int bi = bij >> 1, jh = bij & 1;
    const long rT = (long)bij * 128;

    const u32 aTHI = sa(THI), aTLO = sa(TLO), aPHI = sa(PHI), aPLO = sa(PLO),
              aUHI = sa(UHI), aULO = sa(ULO);

    for (int i = tid; i < 2048; i += 512) {
        int r = i >> 4, c4 = (i & 15) << 2;
        u32 doff = (u32)((r * KPW + c4) * 4);
        cpa16(aTHI + doff, g_Thi + rT * 64 + r * 64 + c4);
        cpa16(aTLO + doff, g_Tlo + rT * 64 + r * 64 + c4);
    }
    if (tid < 128) { srj[tid] = g_rj[rT + tid]; sRow[tid] = 0.f; }
    if (tid < 256) sck[tid] = g_ck[(long)bi * 256 + tid];

    float acc2[2][4][4];
    #pragma unroll
    for (int mf = 0; mf < 2; mf++)
        #pragma unroll
        for (int nf = 0; nf < 4; nf++)
            #pragma unroll
            for (int q = 0; q < 4; q++) acc2[mf][nf][q] = 0.f;

    for (int t2 = 0; t2 < 2; t2++) {
        __syncthreads();   // prev GEMM2 done; (t2==0) srj/sck/sRow visible
        const long sr = ((long)bi * 256 + t2 * 128) * 64;
        for (int i = tid; i < 2048; i += 512) {
            int r = i >> 4, c4 = (i & 15) << 2;
            u32 doff = (u32)((r * KPW + c4) * 4);
            cpa16(aPHI + doff, g_Shi + sr + r * 64 + c4);
            cpa16(aPLO + doff, g_Slo + sr + r * 64 + c4);
            const long go = ((long)bi * 128 + r) * 128 + t2 * 64 + c4;
            cpa16(aUHI + doff, g_Uthi + go);
            cpa16(aULO + doff, g_Utlo + go);
        }
        cpa_wait();
        __syncthreads();

        // GEMM1: scores = T . S^T
        float acc1[2][4][4];
        #pragma unroll
        for (int mf = 0; mf < 2; mf++)
            #pragma unroll
            for (int nf = 0; nf < 4; nf++)
                #pragma unroll
                for (int q = 0; q < 4; q++) acc1[mf][nf][q] = 0.f;
        gemm3p(acc1, aTHI, aTLO, aPHI, aPLO, m0, n0, lane);
        __syncthreads();   // all warps done reading S tile

        // P = relu(scores + rj + ck) -> PHI/PLO, rowsum
        #pragma unroll
        for (int mf = 0; mf < 2; mf++)
            #pragma unroll
            for (int half = 0; half < 2; half++) {
                const int j = m0 + mf * 16 + g + half * 8;
                const float rj = srj[j];
                float rsum = 0.f;
                #pragma unroll
                for (int nf = 0; nf < 4; nf++) {
                    const int kk = n0 + nf * 8 + 2 * t;
                    float p0 = fmaxf(acc1[mf][nf][half * 2]     + rj + sck[t2 * 128 + kk],     0.f);
                    float p1 = fmaxf(acc1[mf][nf][half * 2 + 1] + rj + sck[t2 * 128 + kk + 1], 0.f);
                    rsum += p0 + p1;
                    u32 hw, lw;
                    split2(p0, p1, hw, lw);
                    const int cw = (n0 + nf * 8) / 2 + t;
                    PHI[j * KPW + cw] = hw;
                    PLO[j * KPW + cw] = lw;
                }
                rsum += __shfl_xor_sync(0xFFFFFFFFu, rsum, 1);
                rsum += __shfl_xor_sync(0xFFFFFFFFu, rsum, 2);
                if (t == 0) atomicAdd(&sRow[j], rsum);
            }
        __syncthreads();

        // GEMM2: out += P . U^T
        gemm3p(acc2, aPHI, aPLO, aUHI, aULO, m0, n0, lane);
    }
    __syncthreads();   // sRow final; THI/TLO free

    // epilogue: x = out + rowsum*e + bo + S  -> sx
    const float* Sb = S + ((long)bi * 256 + jh * 128) * D_;
    #pragma unroll
    for (int mf = 0; mf < 2; mf++)
        #pragma unroll
        for (int half = 0; half < 2; half++) {
            const int j = m0 + mf * 16 + g + half * 8;
            const float rs = sRow[j];
            #pragma unroll
            for (int nf = 0; nf < 4; nf++) {
                const int d = n0 + nf * 8 + 2 * t;
                float2 sv = __ldg(reinterpret_cast<const float2*>(&Sb[(long)j * D_ + d]));
                float x0 = acc2[mf][nf][half * 2]     + rs * __ldg(&g_e[d])     + __ldg(&bo[d])     + sv.x;
                float x1 = acc2[mf][nf][half * 2 + 1] + rs * __ldg(&g_e[d + 1]) + __ldg(&bo[d + 1]) + sv.y;
                sx[j * 133 + d]     = x0;
                sx[j * 133 + d + 1] = x1;
            }
        }
    __syncthreads();

    if (tid < 128) {
        float s = 0.f, s2 = 0.f;
        #pragma unroll 8
        for (int d = 0; d < D_; d++) {
            float v = sx[tid * 133 + d];
            s += v; s2 += v * v;
        }
        float mu = s * (1.f / 128.f);
        float var = s2 * (1.f / 128.f) - mu * mu;
        sMu[tid] = mu;
        sRstd[tid] = rsqrtf(var + 1e-5f);
    }
    __syncthreads();

    float* op = out + ((long)bi * 256 + jh * 128) * D_;
    for (int idx = tid; idx < 128 * D_; idx += 512) {
        int j = idx >> 7, d = idx & 127;
        op[idx] = (sx[j * 133 + d] - sMu[j]) * sRstd[j] * __ldg(&ln_g[d]) + __ldg(&ln_b[d]);
    }
}

// =======================================================================
// launch
// =======================================================================
extern "C" void kernel_launch(void* const* d_in, const int* in_sizes, int n_in,
                              void* d_out, int out_size)
{
    (void)in_sizes; (void)n_in; (void)out_size;
    const float* S    = (const float*)d_in[1];
    const float* Wq   = (const float*)d_in[2];
    const float* bq   = (const float*)d_in[3];
    const float* Wk   = (const float*)d_in[4];
    const float* bk   = (const float*)d_in[5];
    const float* Wv   = (const float*)d_in[6];
    const float* bv   = (const float*)d_in[7];
    const float* Wo   = (const float*)d_in[8];
    const float* bo   = (const float*)d_in[9];
    const float* ln_g = (const float*)d_in[10];
    const float* ln_b = (const float*)d_in[11];
    float* out = (float*)d_out;

    const size_t sm0 = (size_t)(128 * 129 + 128) * sizeof(float);
    cudaFuncSetAttribute(k_pre,  cudaFuncAttributeMaxDynamicSharedMemorySize, (int)sm0);
    cudaFuncSetAttribute(k_proj, cudaFuncAttributeMaxDynamicSharedMemorySize, PJ_SMEM);
    cudaFuncSetAttribute(k_attn, cudaFuncAttributeMaxDynamicSharedMemorySize, KA_SMEM);

    k_pre  <<<131, 128, sm0>>>(Wq, bq, Wk, bk, Wv, bv, Wo);
    k_prew <<<1, 256>>>();
    k_split<<<1024, 256>>>(S);
    k_proj <<<1024, 512, PJ_SMEM>>>();
    k_attn <<<1024, 512, KA_SMEM>>>(S, bo, ln_g, ln_b, out);
}